// round 15
// baseline (speedup 1.0000x reference)
#include <cuda_runtime.h>
#include <cuda_bf16.h>
#include <math.h>

#define N_IMG 8
#define CH    100
#define OD    32
#define NC    20
#define HH    256
#define WW    256
#define PIX   (HH*WW)      // 65536

// ---------------- scratch (static device globals; no allocations) ----------------
__device__ float g_xs  [N_IMG*3*PIX];
__device__ float g_fs  [N_IMG*NC*256];
__device__ int   g_lab [N_IMG*PIX];
__device__ float g_sums[N_IMG*OD*NC];
__device__ float g_cnt [N_IMG*OD];
__device__ float g_segw[N_IMG*OD*256];
// bn params: [0,100)=s1 [100,200)=t1 [200,300)=s2 [300,400)=t2 [400,432)=s3 [432,464)=t3
__device__ float g_bnp[464];
// y1 chunks 0-5 (ic 0..95): [(n*6+ch)*PIX + pix]*4 uint4 = 64B/px: h0|h1|l0|l1
__device__ uint4 g_y1c[(size_t)N_IMG*6*PIX*4];
// y1 chunk 6 (ic 96..103, 4 real): [(n*PIX+pix)*2 + {0=h,1=l}] 16B each
__device__ uint4 g_y1c6[(size_t)N_IMG*PIX*2];
// conv2 B fragments k16: [chunk 6][tap 9][tile 14][lane 32] uint4 = {bh0,bh1,bl0,bl1}
__device__ uint4 g_WB[6*9*14*32];
// conv2 B fragments k8 (chunk 6): [tap 9][tile 14][lane 32] uint2 = {bh,bl}
__device__ uint2 g_WB6[9*14*32];

// ======== warp-mma helpers (family-safe PTX, sm_80+) ========
__device__ __forceinline__ unsigned smem_u32(const void* p) {
    unsigned a;
    asm("{ .reg .u64 t; cvta.to.shared.u64 t, %1; cvt.u32.u64 %0, t; }" : "=r"(a) : "l"(p));
    return a;
}
__device__ __forceinline__ void mma16816(float* d, const unsigned* a, unsigned b0, unsigned b1) {
    asm volatile("mma.sync.aligned.m16n8k16.row.col.f32.bf16.bf16.f32 "
        "{%0,%1,%2,%3}, {%4,%5,%6,%7}, {%8,%9}, {%0,%1,%2,%3};"
        : "+f"(d[0]), "+f"(d[1]), "+f"(d[2]), "+f"(d[3])
        : "r"(a[0]), "r"(a[1]), "r"(a[2]), "r"(a[3]), "r"(b0), "r"(b1));
}
__device__ __forceinline__ void mma16808(float* d, const unsigned* a, unsigned b0) {
    asm volatile("mma.sync.aligned.m16n8k8.row.col.f32.bf16.bf16.f32 "
        "{%0,%1,%2,%3}, {%4,%5}, {%6}, {%0,%1,%2,%3};"
        : "+f"(d[0]), "+f"(d[1]), "+f"(d[2]), "+f"(d[3])
        : "r"(a[0]), "r"(a[1]), "r"(b0));
}
__device__ __forceinline__ void ldsm4(unsigned* r, unsigned addr) {
    asm volatile("ldmatrix.sync.aligned.m8n8.x4.shared.b16 {%0,%1,%2,%3}, [%4];"
        : "=r"(r[0]), "=r"(r[1]), "=r"(r[2]), "=r"(r[3]) : "r"(addr));
}
__device__ __forceinline__ void ldsm2(unsigned* r, unsigned addr) {
    asm volatile("ldmatrix.sync.aligned.m8n8.x2.shared.b16 {%0,%1}, [%2];"
        : "=r"(r[0]), "=r"(r[1]) : "r"(addr));
}
__device__ __forceinline__ unsigned pk2(float a, float b) {
    unsigned lo = (unsigned)__bfloat16_as_ushort(__float2bfloat16(a));
    unsigned hi = (unsigned)__bfloat16_as_ushort(__float2bfloat16(b));
    return lo | (hi << 16);
}

// ---------------- antialias tap helper ----------------
__device__ __forceinline__ float d_taps(int d, int* ix, float* wv) {
    float s = 0.f;
    #pragma unroll
    for (int i = 0; i < 4; i++) {
        int p = 2 * d - 1 + i;
        float w = (i == 0 || i == 3) ? 1.f : 3.f;
        if (p < 0 || p >= 512) { w = 0.f; p = p < 0 ? 0 : 511; }
        ix[i] = p; wv[i] = w; s += w;
    }
    return s;
}

// ---------------- mega prep kernel ----------------
// 0-94: k16 weight frags | 95-110: k8 frags | 111: bnprep | 112: zero segw
// 113-6256: downsample | 6257-6416: classifier
__global__ void k_mega(const float* __restrict__ W2,
                       const float* g1, const float* be1, const float* m1, const float* v1,
                       const float* g2, const float* be2, const float* m2, const float* v2,
                       const float* g3, const float* be3, const float* m3, const float* v3,
                       const float* __restrict__ x,
                       const float* __restrict__ x4, const float* __restrict__ Wc,
                       float* __restrict__ cls_out) {
    int b = blockIdx.x, t = threadIdx.x;
    if (b < 95) {
        int idx = b * 256 + t;   // 6*9*14*32 = 24192
        if (idx >= 24192) return;
        int l = idx & 31;
        int j = (idx >> 5) % 14;
        int tap = (idx / (32 * 14)) % 9;
        int c = idx / (32 * 14 * 9);        // 0..5
        int nn = j * 8 + (l >> 2);
        int k0 = (l & 3) * 2;
        float vh[4], vl[4];
        #pragma unroll
        for (int e = 0; e < 4; e++) {
            int k = k0 + (e & 1) + (e >> 1) * 8;
            int ic = c * 16 + k;             // < 96, always real
            float v = (nn < 100) ? W2[nn * 900 + ic * 9 + tap] : 0.f;
            float h = __bfloat162float(__float2bfloat16(v));
            vh[e] = h; vl[e] = v - h;
        }
        uint4 w;
        w.x = pk2(vh[0], vh[1]);
        w.y = pk2(vh[2], vh[3]);
        w.z = pk2(vl[0], vl[1]);
        w.w = pk2(vl[2], vl[3]);
        g_WB[idx] = w;
    } else if (b < 111) {
        int idx = (b - 95) * 256 + t;    // 9*14*32 = 4032
        if (idx >= 4032) return;
        int l = idx & 31;
        int j = (idx >> 5) % 14;
        int tap = idx / (32 * 14);
        int nn = j * 8 + (l >> 2);
        int k0 = (l & 3) * 2;
        float vh[2], vl[2];
        #pragma unroll
        for (int e = 0; e < 2; e++) {
            int ic = 96 + k0 + e;
            float v = (nn < 100 && ic < 100) ? W2[nn * 900 + ic * 9 + tap] : 0.f;
            float h = __bfloat162float(__float2bfloat16(v));
            vh[e] = h; vl[e] = v - h;
        }
        g_WB6[idx] = make_uint2(pk2(vh[0], vh[1]), pk2(vl[0], vl[1]));
    } else if (b == 111) {
        if (t < 100) {
            float s = g1[t] / sqrtf(v1[t] + 1e-5f);
            g_bnp[t] = s; g_bnp[100 + t] = be1[t] - m1[t] * s;
        } else if (t < 200) {
            int i = t - 100;
            float s = g2[i] / sqrtf(v2[i] + 1e-5f);
            g_bnp[200 + i] = s; g_bnp[300 + i] = be2[i] - m2[i] * s;
        } else if (t < 232) {
            int i = t - 200;
            float s = g3[i] / sqrtf(v3[i] + 1e-5f);
            g_bnp[400 + i] = s; g_bnp[432 + i] = be3[i] - m3[i] * s;
        }
    } else if (b == 112) {
        for (int i = t; i < N_IMG * OD * 256; i += 256) g_segw[i] = 0.f;
    } else if (b < 6257) {
        int idx = (b - 113) * 256 + t;
        int xo = idx & 255;
        int yo = (idx >> 8) & 255;
        int nc = idx >> 16;
        int iy[4], ixs[4];
        float wy[4], wx[4];
        float ny = d_taps(yo, iy, wy);
        float nx = d_taps(xo, ixs, wx);
        const float* xp = x + (long)nc * 512 * 512;
        float acc = 0.f;
        #pragma unroll
        for (int i = 0; i < 4; i++) {
            const float* row = xp + iy[i] * 512;
            float r = wx[0]*row[ixs[0]] + wx[1]*row[ixs[1]] + wx[2]*row[ixs[2]] + wx[3]*row[ixs[3]];
            acc += wy[i] * r;
        }
        g_xs[idx] = acc / (ny * nx);
    } else {
        __shared__ float wsh[512];
        __shared__ float red[256];
        int bb = b - 6257;
        int n = bb / NC, oc = bb % NC;
        wsh[t]       = Wc[oc * 512 + t];
        wsh[t + 256] = Wc[oc * 512 + t + 256];
        __syncthreads();
        const float* xp = x4 + (long)n * 512 * 256;
        float acc = 0.f;
        #pragma unroll 8
        for (int c = 0; c < 512; c++) acc = fmaf(xp[c * 256 + t], wsh[c], acc);
        g_fs[(n * NC + oc) * 256 + t] = acc;
        red[t] = acc; __syncthreads();
        for (int s = 128; s > 0; s >>= 1) {
            if (t < s) red[t] = fmaxf(red[t], red[t + s]);
            __syncthreads();
        }
        if (t == 0) cls_out[n * NC + oc] = red[0];
    }
}

// ---------------- conv1: 3x3, 3->100, chunk-major (6x16 + 1x8) ----------
__global__ void k_conv1(const float* __restrict__ W1, const float* __restrict__ b1) {
    __shared__ __align__(16) float ws[2800];
    __shared__ float bs[100], ss[100], ts[100];
    int t = threadIdx.x, n = blockIdx.y;
    for (int i = t; i < 2800; i += 128) {
        int oc = i / 28, j = i - oc * 28;
        ws[i] = (j < 27) ? W1[oc * 27 + j] : 0.f;
    }
    if (t < 100) { bs[t] = b1[t]; ss[t] = g_bnp[t]; ts[t] = g_bnp[100 + t]; }
    __syncthreads();
    int y = blockIdx.x;
    const float* xp = g_xs + n * 3 * PIX;
    float in0[28], in1[28];
    in0[27] = 0.f; in1[27] = 0.f;
    #pragma unroll
    for (int u = 0; u < 2; u++) {
        int x = t + u * 128;
        float* in = u ? in1 : in0;
        int k = 0;
        #pragma unroll
        for (int c = 0; c < 3; c++)
            #pragma unroll
            for (int dy = -1; dy <= 1; dy++) {
                int yy = y + dy;
                #pragma unroll
                for (int dx = -1; dx <= 1; dx++) {
                    int xx = x + dx;
                    in[k++] = ((unsigned)yy < 256u && (unsigned)xx < 256u)
                              ? xp[c * PIX + yy * 256 + xx] : 0.f;
                }
            }
    }
    long cb = (long)(n * 6) * PIX + y * 256;
    for (int ch = 0; ch < 6; ch++) {
        float v0[16], v1[16];
        #pragma unroll
        for (int e = 0; e < 16; e++) {
            int oc = ch * 16 + e;    // < 96, always real
            float bb = bs[oc], sc = ss[oc], sh = ts[oc];
            float a0 = bb, a1 = bb;
            const float4* w4 = (const float4*)(ws + oc * 28);
            #pragma unroll
            for (int q = 0; q < 7; q++) {
                float4 wv = w4[q];
                int j = q * 4;
                a0 = fmaf(in0[j+0], wv.x, a0); a1 = fmaf(in1[j+0], wv.x, a1);
                a0 = fmaf(in0[j+1], wv.y, a0); a1 = fmaf(in1[j+1], wv.y, a1);
                a0 = fmaf(in0[j+2], wv.z, a0); a1 = fmaf(in1[j+2], wv.z, a1);
                a0 = fmaf(in0[j+3], wv.w, a0); a1 = fmaf(in1[j+3], wv.w, a1);
            }
            v0[e] = fmaf(fmaxf(a0, 0.f), sc, sh);
            v1[e] = fmaf(fmaxf(a1, 0.f), sc, sh);
        }
        #pragma unroll
        for (int u = 0; u < 2; u++) {
            float* v = u ? v1 : v0;
            unsigned hw[8], lw[8];
            #pragma unroll
            for (int j2 = 0; j2 < 8; j2++) {
                float a = v[2 * j2], b = v[2 * j2 + 1];
                float ha = __bfloat162float(__float2bfloat16(a));
                float hb = __bfloat162float(__float2bfloat16(b));
                hw[j2] = pk2(a, b);
                lw[j2] = pk2(a - ha, b - hb);
            }
            long pb = (cb + (long)ch * PIX + t + u * 128) * 4;
            g_y1c[pb + 0] = make_uint4(hw[0], hw[1], hw[2], hw[3]);
            g_y1c[pb + 1] = make_uint4(hw[4], hw[5], hw[6], hw[7]);
            g_y1c[pb + 2] = make_uint4(lw[0], lw[1], lw[2], lw[3]);
            g_y1c[pb + 3] = make_uint4(lw[4], lw[5], lw[6], lw[7]);
        }
    }
    // chunk 6: oc 96..103 (4 real)
    {
        float v0[8], v1[8];
        #pragma unroll
        for (int e = 0; e < 8; e++) {
            int oc = 96 + e;
            float a0 = 0.f, a1 = 0.f;
            if (oc < 100) {
                float bb = bs[oc], sc = ss[oc], sh = ts[oc];
                a0 = bb; a1 = bb;
                const float4* w4 = (const float4*)(ws + oc * 28);
                #pragma unroll
                for (int q = 0; q < 7; q++) {
                    float4 wv = w4[q];
                    int j = q * 4;
                    a0 = fmaf(in0[j+0], wv.x, a0); a1 = fmaf(in1[j+0], wv.x, a1);
                    a0 = fmaf(in0[j+1], wv.y, a0); a1 = fmaf(in1[j+1], wv.y, a1);
                    a0 = fmaf(in0[j+2], wv.z, a0); a1 = fmaf(in1[j+2], wv.z, a1);
                    a0 = fmaf(in0[j+3], wv.w, a0); a1 = fmaf(in1[j+3], wv.w, a1);
                }
                a0 = fmaf(fmaxf(a0, 0.f), sc, sh);
                a1 = fmaf(fmaxf(a1, 0.f), sc, sh);
            }
            v0[e] = a0; v1[e] = a1;
        }
        #pragma unroll
        for (int u = 0; u < 2; u++) {
            float* v = u ? v1 : v0;
            unsigned hw[4], lw[4];
            #pragma unroll
            for (int j2 = 0; j2 < 4; j2++) {
                float a = v[2 * j2], b = v[2 * j2 + 1];
                float ha = __bfloat162float(__float2bfloat16(a));
                float hb = __bfloat162float(__float2bfloat16(b));
                hw[j2] = pk2(a, b);
                lw[j2] = pk2(a - ha, b - hb);
            }
            long pb = ((long)n * PIX + y * 256 + t + u * 128) * 2;
            g_y1c6[pb + 0] = make_uint4(hw[0], hw[1], hw[2], hw[3]);
            g_y1c6[pb + 1] = make_uint4(lw[0], lw[1], lw[2], lw[3]);
        }
    }
}

// ---------------- conv2 + conv3 fused: 6x k16 chunks + 1x k8 chunk ----------
#define C2_AH    12480
#define C2_STG   24960
#define C2_SMEM  58368

__global__ __launch_bounds__(256, 2) void k_conv2m(const float* __restrict__ b2,
                                                   const float* __restrict__ W3,
                                                   const float* __restrict__ b3,
                                                   float* __restrict__ out_mask) {
    extern __shared__ __align__(16) unsigned char dsm[];
    __shared__ float sEp[3][112];
    __shared__ float4 w3s4[800];
    __shared__ float p3[96];
    int t = threadIdx.x, lane = t & 31, wid = t >> 5;
    int wm = wid & 3, wn = wid >> 2;
    int jmax = 7 - wn;
    int x0 = blockIdx.x * 128, y = blockIdx.y, n = blockIdx.z;

    if (t < 112) {
        float bb = 0.f, sc = 0.f, sh = 0.f;
        if (t < 100) { bb = b2[t]; sc = g_bnp[200 + t]; sh = g_bnp[300 + t]; }
        sEp[0][t] = bb; sEp[1][t] = sc; sEp[2][t] = sh;
    }
    for (int i = t; i < 800; i += 256) {
        int q = i & 7, c = i >> 3;
        w3s4[i] = make_float4(W3[(4*q+0)*100 + c], W3[(4*q+1)*100 + c],
                              W3[(4*q+2)*100 + c], W3[(4*q+3)*100 + c]);
    }
    if (t < 32) { p3[t] = b3[t]; p3[32 + t] = g_bnp[400 + t]; p3[64 + t] = g_bnp[432 + t]; }

    unsigned base0 = smem_u32(dsm);

    auto stage = [&](int ch, int s) {
        unsigned sb = base0 + s * C2_STG;
        const uint4* gsrc = g_y1c + ((long)(n * 6 + ch) * PIX) * 4;
        for (int i = t; i < 1560; i += 256) {
            int part = i & 3;
            int p = i >> 2;
            int r = p / 130, c = p - r * 130;
            int yy = y - 1 + r, xx = x0 - 1 + c;
            bool ok = ((unsigned)yy < 256u) && ((unsigned)xx < 256u);
            const void* src = ok ? (const void*)(gsrc + ((long)yy * 256 + xx) * 4 + part)
                                 : (const void*)g_y1c;
            int arr = part >> 1, half = part & 1;
            unsigned dst = sb + arr * C2_AH + p * 32 + ((unsigned)((half ^ ((p >> 2) & 1))) << 4);
            unsigned sz = ok ? 16u : 0u;
            asm volatile("cp.async.cg.shared.global [%0], [%1], 16, %2;"
                         :: "r"(dst), "l"(src), "r"(sz));
        }
        asm volatile("cp.async.commit_group;" ::: "memory");
    };
    // chunk-6 stage: 390 px x {h,l} 16B rows into slot s (6240B each region)
    auto stage6 = [&](int s) {
        unsigned sb = base0 + s * C2_STG;
        const uint4* gsrc = g_y1c6 + ((long)n * PIX) * 2;
        for (int i = t; i < 780; i += 256) {
            int arr = i & 1, p = i >> 1;
            int r = p / 130, c = p - r * 130;
            int yy = y - 1 + r, xx = x0 - 1 + c;
            bool ok = ((unsigned)yy < 256u) && ((unsigned)xx < 256u);
            const void* src = ok ? (const void*)(gsrc + ((long)yy * 256 + xx) * 2 + arr)
                                 : (const void*)g_y1c6;
            unsigned dst = sb + arr * 6240 + p * 16;
            unsigned sz = ok ? 16u : 0u;
            asm volatile("cp.async.cg.shared.global [%0], [%1], 16, %2;"
                         :: "r"(dst), "l"(src), "r"(sz));
        }
        asm volatile("cp.async.commit_group;" ::: "memory");
    };

    int arow = lane & 15;
    int akb  = (lane >> 4) & 1;

    float acc[2][7][4];
    #pragma unroll
    for (int s = 0; s < 2; s++)
        #pragma unroll
        for (int j = 0; j < 7; j++)
            #pragma unroll
            for (int e = 0; e < 4; e++) acc[s][j][e] = 0.f;

    stage(0, 0);

    for (int ch = 0; ch < 6; ch++) {
        asm volatile("cp.async.wait_group 0;" ::: "memory");
        __syncthreads();
        if (ch < 5) stage(ch + 1, (ch + 1) & 1);
        else        stage6((ch + 1) & 1);      // chunk 6 into slot 0
        unsigned abase = base0 + (ch & 1) * C2_STG;
        const uint4* wb = g_WB + ch * 9 * 14 * 32;
        #pragma unroll
        for (int tap = 0; tap < 9; tap++) {
            int tg = tap / 3, dxi = tap - tg * 3;
            const uint4* wt = wb + tap * 448 + (wn * 7) * 32 + lane;
            unsigned ah[2][4], al[2][4];
            #pragma unroll
            for (int s2 = 0; s2 < 2; s2++) {
                int pa = tg * 130 + wm * 32 + dxi + s2 * 16 + arow;
                unsigned aoff = (unsigned)(pa * 32 + ((akb ^ ((pa >> 2) & 1)) << 4));
                ldsm4(ah[s2], abase + aoff);
                ldsm4(al[s2], abase + C2_AH + aoff);
            }
            #pragma unroll
            for (int j = 0; j < 7; j++) {
                if (j < jmax) {
                    uint4 w = __ldg(wt + j * 32);
                    #pragma unroll
                    for (int s2 = 0; s2 < 2; s2++) {
                        mma16816(acc[s2][j], ah[s2], w.x, w.y);
                        mma16816(acc[s2][j], al[s2], w.x, w.y);
                        mma16816(acc[s2][j], ah[s2], w.z, w.w);
                    }
                }
            }
        }
    }

    // ---- chunk 6: k8 mma over ic 96..103 ----
    {
        asm volatile("cp.async.wait_group 0;" ::: "memory");
        __syncthreads();
        unsigned abase = base0;   // slot 0
        #pragma unroll
        for (int tap = 0; tap < 9; tap++) {
            int tg = tap / 3, dxi = tap - tg * 3;
            const uint2* wt = g_WB6 + tap * 448 + (wn * 7) * 32 + lane;
            unsigned ah6[2][2], al6[2][2];
            #pragma unroll
            for (int s2 = 0; s2 < 2; s2++) {
                int pa = tg * 130 + wm * 32 + dxi + s2 * 16 + arow;
                ldsm2(ah6[s2], abase + (unsigned)(pa * 16));
                ldsm2(al6[s2], abase + 6240u + (unsigned)(pa * 16));
            }
            #pragma unroll
            for (int j = 0; j < 7; j++) {
                if (j < jmax) {
                    uint2 w = __ldg(wt + j * 32);
                    #pragma unroll
                    for (int s2 = 0; s2 < 2; s2++) {
                        mma16808(acc[s2][j], ah6[s2], w.x);
                        mma16808(acc[s2][j], al6[s2], w.x);
                        mma16808(acc[s2][j], ah6[s2], w.y);
                    }
                }
            }
        }
    }

    // ---- epilogue phase 1: bias + relu + bn -> sY[128][114] ----
    __syncthreads();
    float* sY = (float*)dsm;
    int rbase = wm * 32 + (lane >> 2);
    int ocl = (lane & 3) * 2;
    #pragma unroll
    for (int s = 0; s < 2; s++) {
        #pragma unroll
        for (int j = 0; j < 7; j++) {
            if (j < jmax) {
                int oc0 = (wn * 7 + j) * 8 + ocl;
                float b = sEp[0][oc0],     sc = sEp[1][oc0],     sh = sEp[2][oc0];
                float b1 = sEp[0][oc0+1],  sc1 = sEp[1][oc0+1],  sh1 = sEp[2][oc0+1];
                #pragma unroll
                for (int hh = 0; hh < 2; hh++) {
                    int m = rbase + s * 16 + hh * 8;
                    float v0 = fmaf(fmaxf(acc[s][j][hh*2+0] + b,  0.f), sc,  sh);
                    float v1 = fmaf(fmaxf(acc[s][j][hh*2+1] + b1, 0.f), sc1, sh1);
                    *(float2*)(sY + m * 114 + oc0) = make_float2(v0, v1);
                }
            }
        }
    }
    __syncthreads();

    // ---- epilogue phase 2: conv3 1x1 (100->32) + bn + argmax ----
    {
        int p_loc = t >> 1, grp = t & 1;
        const float* yrow = sY + p_loc * 114;
        float a3[16];
        #pragma unroll
        for (int i = 0; i < 16; i++) a3[i] = 0.f;
        const float4* wq = w3s4 + grp * 4;
        #pragma unroll 4
        for (int c = 0; c < 100; c++) {
            float v = yrow[c];
            float4 w0 = wq[c*8+0], w1 = wq[c*8+1], w2 = wq[c*8+2], w3f = wq[c*8+3];
            a3[0]  = fmaf(v, w0.x, a3[0]);  a3[1]  = fmaf(v, w0.y, a3[1]);
            a3[2]  = fmaf(v, w0.z, a3[2]);  a3[3]  = fmaf(v, w0.w, a3[3]);
            a3[4]  = fmaf(v, w1.x, a3[4]);  a3[5]  = fmaf(v, w1.y, a3[5]);
            a3[6]  = fmaf(v, w1.z, a3[6]);  a3[7]  = fmaf(v, w1.w, a3[7]);
            a3[8]  = fmaf(v, w2.x, a3[8]);  a3[9]  = fmaf(v, w2.y, a3[9]);
            a3[10] = fmaf(v, w2.z, a3[10]); a3[11] = fmaf(v, w2.w, a3[11]);
            a3[12] = fmaf(v, w3f.x, a3[12]); a3[13] = fmaf(v, w3f.y, a3[13]);
            a3[14] = fmaf(v, w3f.z, a3[14]); a3[15] = fmaf(v, w3f.w, a3[15]);
        }
        int pix = y * 256 + x0 + p_loc;
        float best = -INFINITY; int bi = 0;
        #pragma unroll
        for (int i = 0; i < 16; i++) {
            int oc = grp * 16 + i;
            float m = fmaf(a3[i] + p3[oc], p3[32 + oc], p3[64 + oc]);
            out_mask[(long)(n * OD + oc) * PIX + pix] = m;
            if (m > best) { best = m; bi = oc; }
        }
        float obest = __shfl_xor_sync(0xffffffffu, best, 1);
        int   obi   = __shfl_xor_sync(0xffffffffu, bi, 1);
        if (grp == 0) { if (obest > best) { best = obest; bi = obi; } }
        else          { if (obest >= best) { best = obest; bi = obi; } }
        if (grp == 0) g_lab[n * PIX + pix] = bi;
    }
}

// ---------------- segw: per-segment bilinear weight matrix ----------------
__global__ void k_segw() {
    __shared__ float sw[OD * 256];
    int t = threadIdx.x, n = blockIdx.y;
    for (int i = t; i < OD * 256; i += 256) sw[i] = 0.f;
    __syncthreads();

    int x = t;
    float sx = (x + 0.5f) * 0.0625f - 0.5f;
    float fx0 = floorf(sx);
    float fx = sx - fx0;
    int x0 = max((int)fx0, 0), x1 = min((int)fx0 + 1, 15);
    float wx0 = 1.f - fx, wx1 = fx;
    int ybase = blockIdx.x * 16;

    int lab[16];
    #pragma unroll
    for (int yy = 0; yy < 16; yy++)
        lab[yy] = g_lab[n * PIX + (ybase + yy) * 256 + x];

    float A0 = 0.f, A1 = 0.f;
    int curl = -1, cury0 = -1, cury1 = -1;
    #pragma unroll
    for (int yy = 0; yy < 16; yy++) {
        int y = ybase + yy;
        float sy = (y + 0.5f) * 0.0625f - 0.5f;
        float fy0 = floorf(sy);
        float fy = sy - fy0;
        int y0 = max((int)fy0, 0), y1 = min((int)fy0 + 1, 15);
        int l = lab[yy];
        if (l != curl || y0 != cury0 || y1 != cury1) {
            if (curl >= 0) {
                float* swl = sw + curl * 256;
                atomicAdd(&swl[cury0 * 16 + x0], A0 * wx0);
                atomicAdd(&swl[cury0 * 16 + x1], A0 * wx1);
                atomicAdd(&swl[cury1 * 16 + x0], A1 * wx0);
                atomicAdd(&swl[cury1 * 16 + x1], A1 * wx1);
            }
            curl = l; cury0 = y0; cury1 = y1;
            A0 = 1.f - fy; A1 = fy;
        } else {
            A0 += 1.f - fy; A1 += fy;
        }
    }
    if (curl >= 0) {
        float* swl = sw + curl * 256;
        atomicAdd(&swl[cury0 * 16 + x0], A0 * wx0);
        atomicAdd(&swl[cury0 * 16 + x1], A0 * wx1);
        atomicAdd(&swl[cury1 * 16 + x0], A1 * wx0);
        atomicAdd(&swl[cury1 * 16 + x1], A1 * wx1);
    }

    __syncthreads();
    for (int i = t; i < OD * 256; i += 256) {
        float v = sw[i];
        if (v != 0.f) atomicAdd(&g_segw[n * OD * 256 + i], v);
    }
}

// ---------------- finish: sums = W x fs, cnt = rowsum(W), cls_fea ----------------
__global__ void k_finish(float* __restrict__ cls_fea) {
    __shared__ float sfs[NC * 256];
    __shared__ float smean[OD * NC];
    __shared__ float scnt[OD];
    int t = threadIdx.x, n = blockIdx.x;
    for (int i = t; i < NC * 256; i += 256) sfs[i] = g_fs[n * NC * 256 + i];
    __syncthreads();

    const float* Wn = g_segw + n * OD * 256;
    if (t < OD) {
        const float4* wr = (const float4*)(Wn + t * 256);
        float s = 0.f;
        #pragma unroll 8
        for (int q = 0; q < 64; q++) {
            float4 v = wr[q];
            s += v.x + v.y + v.z + v.w;
        }
        scnt[t] = s;
        g_cnt[n * OD + t] = s;
    }
    for (int pair = t; pair < OD * NC; pair += 256) {
        int seg = pair / NC, c = pair - seg * NC;
        const float4* wr = (const float4*)(Wn + seg * 256);
        const float4* fr = (const float4*)(sfs + c * 256);
        float s = 0.f;
        #pragma unroll 8
        for (int q = 0; q < 64; q++) {
            float4 wv = wr[q];
            float4 fv = fr[q];
            s = fmaf(wv.x, fv.x, s);
            s = fmaf(wv.y, fv.y, s);
            s = fmaf(wv.z, fv.z, s);
            s = fmaf(wv.w, fv.w, s);
        }
        g_sums[(n * OD + seg) * NC + c] = s;
        smean[pair] = s;
    }
    __syncthreads();
    if (t < NC) {
        int c = t;
        float m = -INFINITY;
        #pragma unroll 8
        for (int s = 0; s < OD; s++) {
            float cnt = scnt[s];
            if (cnt > 0.f) m = fmaxf(m, smean[s * NC + c] / fmaxf(cnt, 1.f));
        }
        cls_fea[n * NC + c] = m;
    }
}

// ---------------- scatter ----------------
__global__ void k_scatter(float* __restrict__ out_feat) {
    __shared__ float mrow[OD];
    int b = blockIdx.x;
    int nc = b >> 6, seg = b & 63;
    int c = nc % NC, n = nc / NC;
    if (threadIdx.x < OD) {
        int s = threadIdx.x;
        float cnt = g_cnt[n * OD + s];
        mrow[s] = g_sums[(n * OD + s) * NC + c] / fmaxf(cnt, 1.f);
    }
    __syncthreads();
    int p0 = seg * 1024 + threadIdx.x * 4;
    int4 ll = *(const int4*)(g_lab + n * PIX + p0);
    float4 o = make_float4(mrow[ll.x], mrow[ll.y], mrow[ll.z], mrow[ll.w]);
    *(float4*)(out_feat + (long)nc * PIX + p0) = o;
}

// ---------------- launch ----------------
extern "C" void kernel_launch(void* const* d_in, const int* in_sizes, int n_in,
                              void* d_out, int out_size) {
    const float* x   = (const float*)d_in[0];
    const float* x4  = (const float*)d_in[1];
    const float* Wc  = (const float*)d_in[2];
    const float* W1  = (const float*)d_in[3];
    const float* b1c = (const float*)d_in[4];
    const float* g1  = (const float*)d_in[5];
    const float* be1 = (const float*)d_in[6];
    const float* m1  = (const float*)d_in[7];
    const float* v1  = (const float*)d_in[8];
    const float* W2  = (const float*)d_in[9];
    const float* b2c = (const float*)d_in[10];
    const float* g2  = (const float*)d_in[11];
    const float* be2 = (const float*)d_in[12];
    const float* m2  = (const float*)d_in[13];
    const float* v2  = (const float*)d_in[14];
    const float* W3  = (const float*)d_in[15];
    const float* b3c = (const float*)d_in[16];
    const float* g3  = (const float*)d_in[17];
    const float* be3 = (const float*)d_in[18];
    const float* m3  = (const float*)d_in[19];
    const float* v3  = (const float*)d_in[20];

    float* out      = (float*)d_out;
    float* out_cls  = out;
    float* out_cfea = out + 160;
    float* out_feat = out + 320;
    float* out_mask = out + 320 + N_IMG*NC*PIX;

    cudaFuncSetAttribute(k_conv2m, cudaFuncAttributeMaxDynamicSharedMemorySize, C2_SMEM);

    k_mega<<<6417, 256>>>(W2, g1, be1, m1, v1, g2, be2, m2, v2, g3, be3, m3, v3,
                          x, x4, Wc, out_cls);
    k_conv1<<<dim3(256, N_IMG), 128>>>(W1, b1c);
    k_conv2m<<<dim3(2, 256, N_IMG), 256, C2_SMEM>>>(b2c, W3, b3c, out_mask);
    k_segw<<<dim3(16, N_IMG), 256>>>();
    k_finish<<<8, 256>>>(out_cfea);
    k_scatter<<<10240, 256>>>(out_feat);
}

// round 16
// speedup vs baseline: 1.0185x; 1.0185x over previous
#include <cuda_runtime.h>
#include <cuda_bf16.h>
#include <math.h>

#define N_IMG 8
#define CH    100
#define OD    32
#define NC    20
#define HH    256
#define WW    256
#define PIX   (HH*WW)      // 65536

// ---------------- scratch (static device globals; no allocations) ----------------
__device__ float g_xs  [N_IMG*3*PIX];
__device__ float g_fs  [N_IMG*NC*256];
__device__ int   g_lab [N_IMG*PIX];
__device__ float g_sums[N_IMG*OD*NC];
__device__ float g_cnt [N_IMG*OD];
__device__ float g_segw[N_IMG*OD*256];   // W[seg][cell] bilinear weight sums
// bn params: [0,100)=s1 [100,200)=t1 [200,300)=s2 [300,400)=t2 [400,432)=s3 [432,464)=t3
__device__ float g_bnp[464];
// y1 chunk-major: [(n*7+ch)*PIX + pix] * 4 uint4  = 64B per (pixel,chunk): h0|h1|l0|l1
__device__ uint4 g_y1c[(size_t)N_IMG*7*PIX*4];
// conv2 B fragments: [chunk 7][tap 9][tile 14][lane 32] uint4 = {bh0,bh1,bl0,bl1}
__device__ uint4 g_WB[7*9*14*32];

// ======== warp-mma helpers (family-safe PTX, sm_80+) ========
__device__ __forceinline__ unsigned smem_u32(const void* p) {
    unsigned a;
    asm("{ .reg .u64 t; cvta.to.shared.u64 t, %1; cvt.u32.u64 %0, t; }" : "=r"(a) : "l"(p));
    return a;
}
__device__ __forceinline__ void mma16816(float* d, const unsigned* a, unsigned b0, unsigned b1) {
    asm volatile("mma.sync.aligned.m16n8k16.row.col.f32.bf16.bf16.f32 "
        "{%0,%1,%2,%3}, {%4,%5,%6,%7}, {%8,%9}, {%0,%1,%2,%3};"
        : "+f"(d[0]), "+f"(d[1]), "+f"(d[2]), "+f"(d[3])
        : "r"(a[0]), "r"(a[1]), "r"(a[2]), "r"(a[3]), "r"(b0), "r"(b1));
}
__device__ __forceinline__ void ldsm4(unsigned* r, unsigned addr) {
    asm volatile("ldmatrix.sync.aligned.m8n8.x4.shared.b16 {%0,%1,%2,%3}, [%4];"
        : "=r"(r[0]), "=r"(r[1]), "=r"(r[2]), "=r"(r[3]) : "r"(addr));
}
__device__ __forceinline__ unsigned pk2(float a, float b) {
    unsigned lo = (unsigned)__bfloat16_as_ushort(__float2bfloat16(a));
    unsigned hi = (unsigned)__bfloat16_as_ushort(__float2bfloat16(b));
    return lo | (hi << 16);
}

// ---------------- antialias tap helper ----------------
__device__ __forceinline__ float d_taps(int d, int* ix, float* wv) {
    float s = 0.f;
    #pragma unroll
    for (int i = 0; i < 4; i++) {
        int p = 2 * d - 1 + i;
        float w = (i == 0 || i == 3) ? 1.f : 3.f;
        if (p < 0 || p >= 512) { w = 0.f; p = p < 0 ? 0 : 511; }
        ix[i] = p; wv[i] = w; s += w;
    }
    return s;
}

// ---------------- mega prep kernel ----------------
// blocks 0-110: conv2 weight frags | 111: bnprep | 112: zero segw
// blocks 113-6256: antialiased downsample | 6257-6416: classifier 1x1 + max
__global__ void k_mega(const float* __restrict__ W2,
                       const float* g1, const float* be1, const float* m1, const float* v1,
                       const float* g2, const float* be2, const float* m2, const float* v2,
                       const float* g3, const float* be3, const float* m3, const float* v3,
                       const float* __restrict__ x,
                       const float* __restrict__ x4, const float* __restrict__ Wc,
                       float* __restrict__ cls_out) {
    int b = blockIdx.x, t = threadIdx.x;
    if (b < 111) {
        int idx = b * 256 + t;   // 7*9*14*32 = 28224
        if (idx >= 28224) return;
        int l = idx & 31;
        int j = (idx >> 5) % 14;
        int tap = (idx / (32 * 14)) % 9;
        int c = idx / (32 * 14 * 9);
        int nn = j * 8 + (l >> 2);
        int k0 = (l & 3) * 2;
        float vh[4], vl[4];
        #pragma unroll
        for (int e = 0; e < 4; e++) {
            int k = k0 + (e & 1) + (e >> 1) * 8;   // k0, k0+1, k0+8, k0+9
            int ic = c * 16 + k;
            float v = 0.f;
            if (nn < 100 && ic < 100) v = W2[nn * 900 + ic * 9 + tap];
            float h = __bfloat162float(__float2bfloat16(v));
            vh[e] = h; vl[e] = v - h;
        }
        uint4 w;
        w.x = pk2(vh[0], vh[1]);
        w.y = pk2(vh[2], vh[3]);
        w.z = pk2(vl[0], vl[1]);
        w.w = pk2(vl[2], vl[3]);
        g_WB[idx] = w;
    } else if (b == 111) {
        if (t < 100) {
            float s = g1[t] / sqrtf(v1[t] + 1e-5f);
            g_bnp[t] = s; g_bnp[100 + t] = be1[t] - m1[t] * s;
        } else if (t < 200) {
            int i = t - 100;
            float s = g2[i] / sqrtf(v2[i] + 1e-5f);
            g_bnp[200 + i] = s; g_bnp[300 + i] = be2[i] - m2[i] * s;
        } else if (t < 232) {
            int i = t - 200;
            float s = g3[i] / sqrtf(v3[i] + 1e-5f);
            g_bnp[400 + i] = s; g_bnp[432 + i] = be3[i] - m3[i] * s;
        }
    } else if (b == 112) {
        for (int i = t; i < N_IMG * OD * 256; i += 256) g_segw[i] = 0.f;
    } else if (b < 6257) {
        // downsample
        int idx = (b - 113) * 256 + t;
        int xo = idx & 255;
        int yo = (idx >> 8) & 255;
        int nc = idx >> 16;
        int iy[4], ixs[4];
        float wy[4], wx[4];
        float ny = d_taps(yo, iy, wy);
        float nx = d_taps(xo, ixs, wx);
        const float* xp = x + (long)nc * 512 * 512;
        float acc = 0.f;
        #pragma unroll
        for (int i = 0; i < 4; i++) {
            const float* row = xp + iy[i] * 512;
            float r = wx[0]*row[ixs[0]] + wx[1]*row[ixs[1]] + wx[2]*row[ixs[2]] + wx[3]*row[ixs[3]];
            acc += wy[i] * r;
        }
        g_xs[idx] = acc / (ny * nx);
    } else {
        // classifier
        __shared__ float wsh[512];
        __shared__ float red[256];
        int bb = b - 6257;
        int n = bb / NC, oc = bb % NC;
        wsh[t]       = Wc[oc * 512 + t];
        wsh[t + 256] = Wc[oc * 512 + t + 256];
        __syncthreads();
        const float* xp = x4 + (long)n * 512 * 256;
        float acc = 0.f;
        #pragma unroll 8
        for (int c = 0; c < 512; c++) acc = fmaf(xp[c * 256 + t], wsh[c], acc);
        g_fs[(n * NC + oc) * 256 + t] = acc;
        red[t] = acc; __syncthreads();
        for (int s = 128; s > 0; s >>= 1) {
            if (t < s) red[t] = fmaxf(red[t], red[t + s]);
            __syncthreads();
        }
        if (t == 0) cls_out[n * NC + oc] = red[0];
    }
}

// ---------------- conv1: 3x3, 3->100, 2 px/thread, float4 weight loads ----------
__global__ void k_conv1(const float* __restrict__ W1, const float* __restrict__ b1) {
    __shared__ __align__(16) float ws[2800];
    __shared__ float bs[100], ss[100], ts[100];
    int t = threadIdx.x, n = blockIdx.y;
    for (int i = t; i < 2800; i += 128) {
        int oc = i / 28, j = i - oc * 28;
        ws[i] = (j < 27) ? W1[oc * 27 + j] : 0.f;
    }
    if (t < 100) { bs[t] = b1[t]; ss[t] = g_bnp[t]; ts[t] = g_bnp[100 + t]; }
    __syncthreads();
    int y = blockIdx.x;
    const float* xp = g_xs + n * 3 * PIX;
    float in0[28], in1[28];
    in0[27] = 0.f; in1[27] = 0.f;
    #pragma unroll
    for (int u = 0; u < 2; u++) {
        int x = t + u * 128;
        float* in = u ? in1 : in0;
        int k = 0;
        #pragma unroll
        for (int c = 0; c < 3; c++)
            #pragma unroll
            for (int dy = -1; dy <= 1; dy++) {
                int yy = y + dy;
                #pragma unroll
                for (int dx = -1; dx <= 1; dx++) {
                    int xx = x + dx;
                    in[k++] = ((unsigned)yy < 256u && (unsigned)xx < 256u)
                              ? xp[c * PIX + yy * 256 + xx] : 0.f;
                }
            }
    }
    long cb = (long)(n * 7) * PIX + y * 256;
    for (int ch = 0; ch < 7; ch++) {
        float v0[16], v1[16];
        #pragma unroll
        for (int e = 0; e < 16; e++) {
            int oc = ch * 16 + e;
            float a0 = 0.f, a1 = 0.f;
            if (oc < 100) {
                float bb = bs[oc], sc = ss[oc], sh = ts[oc];
                a0 = bb; a1 = bb;
                const float4* w4 = (const float4*)(ws + oc * 28);
                #pragma unroll
                for (int q = 0; q < 7; q++) {
                    float4 wv = w4[q];
                    int j = q * 4;
                    a0 = fmaf(in0[j+0], wv.x, a0); a1 = fmaf(in1[j+0], wv.x, a1);
                    a0 = fmaf(in0[j+1], wv.y, a0); a1 = fmaf(in1[j+1], wv.y, a1);
                    a0 = fmaf(in0[j+2], wv.z, a0); a1 = fmaf(in1[j+2], wv.z, a1);
                    a0 = fmaf(in0[j+3], wv.w, a0); a1 = fmaf(in1[j+3], wv.w, a1);
                }
                a0 = fmaf(fmaxf(a0, 0.f), sc, sh);
                a1 = fmaf(fmaxf(a1, 0.f), sc, sh);
            }
            v0[e] = a0; v1[e] = a1;
        }
        #pragma unroll
        for (int u = 0; u < 2; u++) {
            float* v = u ? v1 : v0;
            unsigned hw[8], lw[8];
            #pragma unroll
            for (int j2 = 0; j2 < 8; j2++) {
                float a = v[2 * j2], b = v[2 * j2 + 1];
                float ha = __bfloat162float(__float2bfloat16(a));
                float hb = __bfloat162float(__float2bfloat16(b));
                hw[j2] = pk2(a, b);
                lw[j2] = pk2(a - ha, b - hb);
            }
            long pb = (cb + (long)ch * PIX + t + u * 128) * 4;
            g_y1c[pb + 0] = make_uint4(hw[0], hw[1], hw[2], hw[3]);
            g_y1c[pb + 1] = make_uint4(hw[4], hw[5], hw[6], hw[7]);
            g_y1c[pb + 2] = make_uint4(lw[0], lw[1], lw[2], lw[3]);
            g_y1c[pb + 3] = make_uint4(lw[4], lw[5], lw[6], lw[7]);
        }
    }
}

// ---------------- conv2 + conv3 fused: mma implicit GEMM (2-stage) ----------
#define C2_AH    12480
#define C2_STG   24960
#define C2_SMEM  58368

__global__ __launch_bounds__(256, 2) void k_conv2m(const float* __restrict__ b2,
                                                   const float* __restrict__ W3,
                                                   const float* __restrict__ b3,
                                                   float* __restrict__ out_mask) {
    extern __shared__ __align__(16) unsigned char dsm[];
    __shared__ float sEp[3][112];
    __shared__ float4 w3s4[800];   // [c][q] -> oc 4q..4q+3
    __shared__ float p3[96];
    int t = threadIdx.x, lane = t & 31, wid = t >> 5;
    int wm = wid & 3, wn = wid >> 2;
    int jmax = 7 - wn;             // wn0: tiles 0-6, wn1: tiles 7-12
    int x0 = blockIdx.x * 128, y = blockIdx.y, n = blockIdx.z;

    if (t < 112) {
        float bb = 0.f, sc = 0.f, sh = 0.f;
        if (t < 100) { bb = b2[t]; sc = g_bnp[200 + t]; sh = g_bnp[300 + t]; }
        sEp[0][t] = bb; sEp[1][t] = sc; sEp[2][t] = sh;
    }
    for (int i = t; i < 800; i += 256) {
        int q = i & 7, c = i >> 3;
        w3s4[i] = make_float4(W3[(4*q+0)*100 + c], W3[(4*q+1)*100 + c],
                              W3[(4*q+2)*100 + c], W3[(4*q+3)*100 + c]);
    }
    if (t < 32) { p3[t] = b3[t]; p3[32 + t] = g_bnp[400 + t]; p3[64 + t] = g_bnp[432 + t]; }

    unsigned base0 = smem_u32(dsm);

    auto stage = [&](int ch, int s) {
        unsigned sb = base0 + s * C2_STG;
        const uint4* gsrc = g_y1c + ((long)(n * 7 + ch) * PIX) * 4;
        for (int i = t; i < 1560; i += 256) {
            int part = i & 3;                // 0,1=h ; 2,3=l
            int p = i >> 2;                  // 0..389
            int r = p / 130, c = p - r * 130;
            int yy = y - 1 + r, xx = x0 - 1 + c;
            bool ok = ((unsigned)yy < 256u) && ((unsigned)xx < 256u);
            const void* src = ok ? (const void*)(gsrc + ((long)yy * 256 + xx) * 4 + part)
                                 : (const void*)g_y1c;
            int arr = part >> 1, half = part & 1;
            unsigned dst = sb + arr * C2_AH + p * 32 + ((unsigned)((half ^ ((p >> 2) & 1))) << 4);
            unsigned sz = ok ? 16u : 0u;
            asm volatile("cp.async.cg.shared.global [%0], [%1], 16, %2;"
                         :: "r"(dst), "l"(src), "r"(sz));
        }
        asm volatile("cp.async.commit_group;" ::: "memory");
    };

    int arow = lane & 15;
    int akb  = (lane >> 4) & 1;

    float acc[2][7][4];
    #pragma unroll
    for (int s = 0; s < 2; s++)
        #pragma unroll
        for (int j = 0; j < 7; j++)
            #pragma unroll
            for (int e = 0; e < 4; e++) acc[s][j][e] = 0.f;

    stage(0, 0);

    for (int ch = 0; ch < 7; ch++) {
        asm volatile("cp.async.wait_group 0;" ::: "memory");
        __syncthreads();
        if (ch < 6) stage(ch + 1, (ch + 1) & 1);
        unsigned abase = base0 + (ch & 1) * C2_STG;
        const uint4* wb = g_WB + ch * 9 * 14 * 32;
        #pragma unroll
        for (int tap = 0; tap < 9; tap++) {
            int tg = tap / 3, dxi = tap - tg * 3;
            const uint4* wt = wb + tap * 448 + (wn * 7) * 32 + lane;
            unsigned ah[2][4], al[2][4];
            #pragma unroll
            for (int s2 = 0; s2 < 2; s2++) {
                int pa = tg * 130 + wm * 32 + dxi + s2 * 16 + arow;
                unsigned aoff = (unsigned)(pa * 32 + ((akb ^ ((pa >> 2) & 1)) << 4));
                ldsm4(ah[s2], abase + aoff);
                ldsm4(al[s2], abase + C2_AH + aoff);
            }
            #pragma unroll
            for (int j = 0; j < 7; j++) {
                if (j < jmax) {
                    uint4 w = __ldg(wt + j * 32);
                    #pragma unroll
                    for (int s2 = 0; s2 < 2; s2++) {
                        mma16816(acc[s2][j], ah[s2], w.x, w.y);
                        mma16816(acc[s2][j], al[s2], w.x, w.y);
                        mma16816(acc[s2][j], ah[s2], w.z, w.w);
                    }
                }
            }
        }
    }

    // ---- epilogue phase 1: bias + relu + bn -> sY[128][114] ----
    __syncthreads();
    float* sY = (float*)dsm;
    int rbase = wm * 32 + (lane >> 2);
    int ocl = (lane & 3) * 2;
    #pragma unroll
    for (int s = 0; s < 2; s++) {
        #pragma unroll
        for (int j = 0; j < 7; j++) {
            if (j < jmax) {
                int oc0 = (wn * 7 + j) * 8 + ocl;
                float b = sEp[0][oc0],     sc = sEp[1][oc0],     sh = sEp[2][oc0];
                float b1 = sEp[0][oc0+1],  sc1 = sEp[1][oc0+1],  sh1 = sEp[2][oc0+1];
                #pragma unroll
                for (int hh = 0; hh < 2; hh++) {
                    int m = rbase + s * 16 + hh * 8;
                    float v0 = fmaf(fmaxf(acc[s][j][hh*2+0] + b,  0.f), sc,  sh);
                    float v1 = fmaf(fmaxf(acc[s][j][hh*2+1] + b1, 0.f), sc1, sh1);
                    *(float2*)(sY + m * 114 + oc0) = make_float2(v0, v1);
                }
            }
        }
    }
    __syncthreads();

    // ---- epilogue phase 2: conv3 1x1 (100->32) + bn + argmax ----
    {
        int p_loc = t >> 1, grp = t & 1;
        const float* yrow = sY + p_loc * 114;
        float a3[16];
        #pragma unroll
        for (int i = 0; i < 16; i++) a3[i] = 0.f;
        const float4* wq = w3s4 + grp * 4;
        #pragma unroll 4
        for (int c = 0; c < 100; c++) {
            float v = yrow[c];
            float4 w0 = wq[c*8+0], w1 = wq[c*8+1], w2 = wq[c*8+2], w3f = wq[c*8+3];
            a3[0]  = fmaf(v, w0.x, a3[0]);  a3[1]  = fmaf(v, w0.y, a3[1]);
            a3[2]  = fmaf(v, w0.z, a3[2]);  a3[3]  = fmaf(v, w0.w, a3[3]);
            a3[4]  = fmaf(v, w1.x, a3[4]);  a3[5]  = fmaf(v, w1.y, a3[5]);
            a3[6]  = fmaf(v, w1.z, a3[6]);  a3[7]  = fmaf(v, w1.w, a3[7]);
            a3[8]  = fmaf(v, w2.x, a3[8]);  a3[9]  = fmaf(v, w2.y, a3[9]);
            a3[10] = fmaf(v, w2.z, a3[10]); a3[11] = fmaf(v, w2.w, a3[11]);
            a3[12] = fmaf(v, w3f.x, a3[12]); a3[13] = fmaf(v, w3f.y, a3[13]);
            a3[14] = fmaf(v, w3f.z, a3[14]); a3[15] = fmaf(v, w3f.w, a3[15]);
        }
        int pix = y * 256 + x0 + p_loc;
        float best = -INFINITY; int bi = 0;
        #pragma unroll
        for (int i = 0; i < 16; i++) {
            int oc = grp * 16 + i;
            float m = fmaf(a3[i] + p3[oc], p3[32 + oc], p3[64 + oc]);
            out_mask[(long)(n * OD + oc) * PIX + pix] = m;
            if (m > best) { best = m; bi = oc; }
        }
        float obest = __shfl_xor_sync(0xffffffffu, best, 1);
        int   obi   = __shfl_xor_sync(0xffffffffu, bi, 1);
        if (grp == 0) { if (obest > best) { best = obest; bi = obi; } }
        else          { if (obest >= best) { best = obest; bi = obi; } }
        if (grp == 0) g_lab[n * PIX + pix] = bi;
    }
}

// ---------------- segw: accumulate per-segment bilinear WEIGHT matrix ----------------
// grid (16, 8), 256 threads: thread = column x, 16 rows per block.
__global__ void k_segw() {
    __shared__ float sw[OD * 256];   // 32KB
    int t = threadIdx.x, n = blockIdx.y;
    for (int i = t; i < OD * 256; i += 256) sw[i] = 0.f;
    __syncthreads();

    int x = t;
    float sx = (x + 0.5f) * 0.0625f - 0.5f;
    float fx0 = floorf(sx);
    float fx = sx - fx0;
    int x0 = max((int)fx0, 0), x1 = min((int)fx0 + 1, 15);
    float wx0 = 1.f - fx, wx1 = fx;
    int ybase = blockIdx.x * 16;

    // batch label loads (independent, MLP=16)
    int lab[16];
    #pragma unroll
    for (int yy = 0; yy < 16; yy++)
        lab[yy] = g_lab[n * PIX + (ybase + yy) * 256 + x];

    float A0 = 0.f, A1 = 0.f;
    int curl = -1, cury0 = -1, cury1 = -1;
    #pragma unroll
    for (int yy = 0; yy < 16; yy++) {
        int y = ybase + yy;
        float sy = (y + 0.5f) * 0.0625f - 0.5f;
        float fy0 = floorf(sy);
        float fy = sy - fy0;
        int y0 = max((int)fy0, 0), y1 = min((int)fy0 + 1, 15);
        int l = lab[yy];
        if (l != curl || y0 != cury0 || y1 != cury1) {   // y1 check handles clamp boundary
            if (curl >= 0) {
                float* swl = sw + curl * 256;
                atomicAdd(&swl[cury0 * 16 + x0], A0 * wx0);
                atomicAdd(&swl[cury0 * 16 + x1], A0 * wx1);
                atomicAdd(&swl[cury1 * 16 + x0], A1 * wx0);
                atomicAdd(&swl[cury1 * 16 + x1], A1 * wx1);
            }
            curl = l; cury0 = y0; cury1 = y1;
            A0 = 1.f - fy; A1 = fy;
        } else {
            A0 += 1.f - fy; A1 += fy;
        }
    }
    if (curl >= 0) {
        float* swl = sw + curl * 256;
        atomicAdd(&swl[cury0 * 16 + x0], A0 * wx0);
        atomicAdd(&swl[cury0 * 16 + x1], A0 * wx1);
        atomicAdd(&swl[cury1 * 16 + x0], A1 * wx0);
        atomicAdd(&swl[cury1 * 16 + x1], A1 * wx1);
    }

    __syncthreads();
    for (int i = t; i < OD * 256; i += 256) {
        float v = sw[i];
        if (v != 0.f) atomicAdd(&g_segw[n * OD * 256 + i], v);
    }
}

// ---------------- finish: sums = W x fs, cnt = rowsum(W), cls_fea ----------------
// grid 8 (one block per image), 256 threads
__global__ void k_finish(float* __restrict__ cls_fea) {
    __shared__ float sfs[NC * 256];     // 20KB
    __shared__ float smean[OD * NC];
    __shared__ float scnt[OD];
    int t = threadIdx.x, n = blockIdx.x;
    for (int i = t; i < NC * 256; i += 256) sfs[i] = g_fs[n * NC * 256 + i];
    __syncthreads();

    const float* Wn = g_segw + n * OD * 256;
    if (t < OD) {
        const float4* wr = (const float4*)(Wn + t * 256);
        float s = 0.f;
        #pragma unroll 8
        for (int q = 0; q < 64; q++) {
            float4 v = wr[q];
            s += v.x + v.y + v.z + v.w;
        }
        scnt[t] = s;
        g_cnt[n * OD + t] = s;
    }
    for (int pair = t; pair < OD * NC; pair += 256) {
        int seg = pair / NC, c = pair - seg * NC;
        const float4* wr = (const float4*)(Wn + seg * 256);
        const float4* fr = (const float4*)(sfs + c * 256);
        float s = 0.f;
        #pragma unroll 8
        for (int q = 0; q < 64; q++) {
            float4 wv = wr[q];
            float4 fv = fr[q];
            s = fmaf(wv.x, fv.x, s);
            s = fmaf(wv.y, fv.y, s);
            s = fmaf(wv.z, fv.z, s);
            s = fmaf(wv.w, fv.w, s);
        }
        g_sums[(n * OD + seg) * NC + c] = s;
        smean[pair] = s;
    }
    __syncthreads();
    if (t < NC) {
        int c = t;
        float m = -INFINITY;
        #pragma unroll 8
        for (int s = 0; s < OD; s++) {
            float cnt = scnt[s];
            if (cnt > 0.f) m = fmaxf(m, smean[s * NC + c] / fmaxf(cnt, 1.f));
        }
        cls_fea[n * NC + c] = m;
    }
}

// ---------------- scatter: local means row + int4/float4 I/O ----------------
__global__ void k_scatter(float* __restrict__ out_feat) {
    __shared__ float mrow[OD];
    int b = blockIdx.x;
    int nc = b >> 6, seg = b & 63;
    int c = nc % NC, n = nc / NC;
    if (threadIdx.x < OD) {
        int s = threadIdx.x;
        float cnt = g_cnt[n * OD + s];
        mrow[s] = g_sums[(n * OD + s) * NC + c] / fmaxf(cnt, 1.f);
    }
    __syncthreads();
    int p0 = seg * 1024 + threadIdx.x * 4;
    int4 ll = *(const int4*)(g_lab + n * PIX + p0);
    float4 o = make_float4(mrow[ll.x], mrow[ll.y], mrow[ll.z], mrow[ll.w]);
    *(float4*)(out_feat + (long)nc * PIX + p0) = o;
}

// ---------------- launch ----------------
extern "C" void kernel_launch(void* const* d_in, const int* in_sizes, int n_in,
                              void* d_out, int out_size) {
    const float* x   = (const float*)d_in[0];
    const float* x4  = (const float*)d_in[1];
    const float* Wc  = (const float*)d_in[2];
    const float* W1  = (const float*)d_in[3];
    const float* b1c = (const float*)d_in[4];
    const float* g1  = (const float*)d_in[5];
    const float* be1 = (const float*)d_in[6];
    const float* m1  = (const float*)d_in[7];
    const float* v1  = (const float*)d_in[8];
    const float* W2  = (const float*)d_in[9];
    const float* b2c = (const float*)d_in[10];
    const float* g2  = (const float*)d_in[11];
    const float* be2 = (const float*)d_in[12];
    const float* m2  = (const float*)d_in[13];
    const float* v2  = (const float*)d_in[14];
    const float* W3  = (const float*)d_in[15];
    const float* b3c = (const float*)d_in[16];
    const float* g3  = (const float*)d_in[17];
    const float* be3 = (const float*)d_in[18];
    const float* m3  = (const float*)d_in[19];
    const float* v3  = (const float*)d_in[20];

    float* out      = (float*)d_out;
    float* out_cls  = out;
    float* out_cfea = out + 160;
    float* out_feat = out + 320;
    float* out_mask = out + 320 + N_IMG*NC*PIX;

    cudaFuncSetAttribute(k_conv2m, cudaFuncAttributeMaxDynamicSharedMemorySize, C2_SMEM);

    k_mega<<<6417, 256>>>(W2, g1, be1, m1, v1, g2, be2, m2, v2, g3, be3, m3, v3,
                          x, x4, Wc, out_cls);
    k_conv1<<<dim3(256, N_IMG), 128>>>(W1, b1c);
    k_conv2m<<<dim3(2, 256, N_IMG), 256, C2_SMEM>>>(b2c, W3, b3c, out_mask);
    k_segw<<<dim3(16, N_IMG), 256>>>();
    k_finish<<<8, 256>>>(out_cfea);
    k_scatter<<<10240, 256>>>(out_feat);
}